// round 1
// baseline (speedup 1.0000x reference)
#include <cuda_runtime.h>
#include <cuda_bf16.h>
#include <cstdint>

// ---------------------------------------------------------------------------
// GATv2, 3 layers.  N=20000 nodes, E=320000 edges.
// L0: IN=128 -> H0=4 x 64   (no residual, ELU)
// L1: 256    -> H1=4 x 64   (identity residual, ELU)
// L2: 256    -> H2=6 x 32   (linear residual Wr2, no act), mean over heads.
// ---------------------------------------------------------------------------

#define N_MAX   20000
#define E_MAX   320000
#define SLOPE   0.2f

// Scratch (device globals; no allocation allowed)
__device__ __align__(16) float g_FS[N_MAX * 256];
__device__ __align__(16) float g_FD[N_MAX * 256];
__device__ __align__(16) float g_HA[N_MAX * 256];
__device__ __align__(16) float g_HB[N_MAX * 256];
__device__ __align__(16) float g_EX[E_MAX * 6];
__device__              int   g_M [N_MAX * 6];
__device__              float g_DEN[N_MAX * 6];

static inline int cdiv(int a, int b) { return (a + b - 1) / b; }

// ---------------------------------------------------------------------------
// SGEMM: C[N x M] = A[N x K] @ W[K x M] + bias.  K % 16 == 0, M % 64 == 0.
// 64x64 tile, 256 threads, 4x4 per-thread micro-tile.
// ---------------------------------------------------------------------------
#define BM 64
#define BN 64
#define BK 16

__global__ __launch_bounds__(256) void gemm_bias_kernel(
    const float* __restrict__ A, const float* __restrict__ W,
    const float* __restrict__ bias, float* __restrict__ C,
    int Nrows, int K, int M)
{
    __shared__ float As[BK][BM];
    __shared__ float Wsm[BK][BN];

    const int tid = threadIdx.x;
    const int rowBase = blockIdx.x * BM;
    const int colBase = blockIdx.y * BN;

    const int tr = (tid / 16) * 4;
    const int tc = (tid % 16) * 4;

    float acc[4][4] = {};

    const int aRow = tid / 4;        // 0..63
    const int aK   = (tid % 4) * 4;  // 0,4,8,12
    const int wRow = tid / 16;       // 0..15
    const int wCol = (tid % 16) * 4; // 0..60

    for (int k0 = 0; k0 < K; k0 += BK) {
        float4 av = make_float4(0.f, 0.f, 0.f, 0.f);
        int gr = rowBase + aRow;
        if (gr < Nrows)
            av = *reinterpret_cast<const float4*>(&A[(size_t)gr * K + k0 + aK]);
        As[aK + 0][aRow] = av.x;
        As[aK + 1][aRow] = av.y;
        As[aK + 2][aRow] = av.z;
        As[aK + 3][aRow] = av.w;

        float4 wv = *reinterpret_cast<const float4*>(&W[(size_t)(k0 + wRow) * M + colBase + wCol]);
        *reinterpret_cast<float4*>(&Wsm[wRow][wCol]) = wv;

        __syncthreads();

        #pragma unroll
        for (int k = 0; k < BK; k++) {
            float ar[4], wr[4];
            #pragma unroll
            for (int i = 0; i < 4; i++) ar[i] = As[k][tr + i];
            #pragma unroll
            for (int j = 0; j < 4; j++) wr[j] = Wsm[k][tc + j];
            #pragma unroll
            for (int i = 0; i < 4; i++)
                #pragma unroll
                for (int j = 0; j < 4; j++)
                    acc[i][j] += ar[i] * wr[j];
        }
        __syncthreads();
    }

    float4 bv = *reinterpret_cast<const float4*>(&bias[colBase + tc]);
    #pragma unroll
    for (int i = 0; i < 4; i++) {
        int gr = rowBase + tr + i;
        if (gr >= Nrows) continue;
        float4 v;
        v.x = acc[i][0] + bv.x;
        v.y = acc[i][1] + bv.y;
        v.z = acc[i][2] + bv.z;
        v.w = acc[i][3] + bv.w;
        *reinterpret_cast<float4*>(&C[(size_t)gr * M + colBase + tc]) = v;
    }
}

// ---------------------------------------------------------------------------
// Edge softmax helpers
// ---------------------------------------------------------------------------
__device__ __forceinline__ int enc_f(float f) {
    int i = __float_as_int(f);
    return (i >= 0) ? i : (i ^ 0x7fffffff);
}
__device__ __forceinline__ float dec_f(int i) {
    return __int_as_float((i >= 0) ? i : (i ^ 0x7fffffff));
}

__global__ void init_md_kernel(int* mEnc, float* denom, int n) {
    int i = blockIdx.x * blockDim.x + threadIdx.x;
    if (i < n) { mEnc[i] = (int)0x80000000; denom[i] = 0.f; }
}

__global__ void fill_zero_kernel(float4* p, int n4) {
    int i = blockIdx.x * blockDim.x + threadIdx.x;
    if (i < n4) p[i] = make_float4(0.f, 0.f, 0.f, 0.f);
}

__global__ void copy_kernel(float4* d, const float4* s, int n4) {
    int i = blockIdx.x * blockDim.x + threadIdx.x;
    if (i < n4) d[i] = s[i];
}

// Pass A: logits + segment max (atomicMax on ordered-int encoding)
template <int H, int D>
__global__ void edge_logits_kernel(
    const int* __restrict__ src, const int* __restrict__ dst,
    const float* __restrict__ FS, const float* __restrict__ FD,
    const float* __restrict__ attn,
    float* __restrict__ logit, int* __restrict__ mEnc, int E)
{
    int i = blockIdx.x * blockDim.x + threadIdx.x;
    if (i >= E * H) return;
    int e = i / H, h = i % H;
    int s = src[e], d = dst[e];

    const float4* fs = reinterpret_cast<const float4*>(&FS[(size_t)s * (H * D) + h * D]);
    const float4* fd = reinterpret_cast<const float4*>(&FD[(size_t)d * (H * D) + h * D]);
    const float4* at = reinterpret_cast<const float4*>(&attn[h * D]);

    float acc = 0.f;
    #pragma unroll
    for (int q = 0; q < D / 4; q++) {
        float4 a = fs[q], b = fd[q], c = at[q];
        float v;
        v = a.x + b.x; v = (v > 0.f) ? v : SLOPE * v; acc += v * c.x;
        v = a.y + b.y; v = (v > 0.f) ? v : SLOPE * v; acc += v * c.y;
        v = a.z + b.z; v = (v > 0.f) ? v : SLOPE * v; acc += v * c.z;
        v = a.w + b.w; v = (v > 0.f) ? v : SLOPE * v; acc += v * c.w;
    }
    logit[i] = acc;
    atomicMax(&mEnc[d * H + h], enc_f(acc));
}

// Pass B: ex = exp(logit - max), denom += ex
template <int H>
__global__ void edge_exp_kernel(
    const int* __restrict__ dst, float* __restrict__ logit,
    const int* __restrict__ mEnc, float* __restrict__ denom, int E)
{
    int i = blockIdx.x * blockDim.x + threadIdx.x;
    if (i >= E * H) return;
    int e = i / H, h = i % H;
    int d = dst[e];
    float m = dec_f(mEnc[d * H + h]);
    float ex = __expf(logit[i] - m);
    logit[i] = ex;
    atomicAdd(&denom[d * H + h], ex);
}

// Pass C: out[dst] += feat_src[src] * alpha  (vector red.global.add.v4.f32)
template <int H, int D>
__global__ void edge_scatter_kernel(
    const int* __restrict__ src, const int* __restrict__ dst,
    const float* __restrict__ FS, const float* __restrict__ ex,
    const float* __restrict__ denom, float* __restrict__ out, int E)
{
    int i = blockIdx.x * blockDim.x + threadIdx.x;
    if (i >= E * H) return;
    int e = i / H, h = i % H;
    int s = src[e], d = dst[e];
    float alpha = ex[i] / denom[d * H + h];

    const float4* fs = reinterpret_cast<const float4*>(&FS[(size_t)s * (H * D) + h * D]);
    float* ob = &out[(size_t)d * (H * D) + h * D];

    #pragma unroll
    for (int q = 0; q < D / 4; q++) {
        float4 a = fs[q];
        asm volatile("red.global.add.v4.f32 [%0], {%1,%2,%3,%4};"
                     :: "l"(ob + q * 4),
                        "f"(a.x * alpha), "f"(a.y * alpha),
                        "f"(a.z * alpha), "f"(a.w * alpha)
                     : "memory");
    }
}

__global__ void elu_kernel(float* __restrict__ p, int n) {
    int i = blockIdx.x * blockDim.x + threadIdx.x;
    if (i >= n) return;
    float v = p[i];
    p[i] = (v > 0.f) ? v : expm1f(v);
}

// mean over H2=6 heads of [N, 6, 32] -> [N, 32]
__global__ void mean_heads_kernel(const float* __restrict__ in, float* __restrict__ out, int n) {
    int i = blockIdx.x * blockDim.x + threadIdx.x;
    if (i >= n) return;
    int node = i / 32, c = i % 32;
    const float* row = &in[(size_t)node * 192 + c];
    float s = 0.f;
    #pragma unroll
    for (int h = 0; h < 6; h++) s += row[h * 32];
    out[i] = s * (1.f / 6.f);
}

// ---------------------------------------------------------------------------
// Host driver
// ---------------------------------------------------------------------------
extern "C" void kernel_launch(void* const* d_in, const int* in_sizes, int n_in,
                              void* d_out, int out_size)
{
    const float* x   = (const float*)d_in[0];
    const int*   src = (const int*)d_in[1];
    const int*   dst = (const int*)d_in[2];
    const float* W0s = (const float*)d_in[3];
    const float* b0s = (const float*)d_in[4];
    const float* W0d = (const float*)d_in[5];
    const float* b0d = (const float*)d_in[6];
    const float* a0  = (const float*)d_in[7];
    const float* W1s = (const float*)d_in[8];
    const float* b1s = (const float*)d_in[9];
    const float* W1d = (const float*)d_in[10];
    const float* b1d = (const float*)d_in[11];
    const float* a1  = (const float*)d_in[12];
    const float* W2s = (const float*)d_in[13];
    const float* b2s = (const float*)d_in[14];
    const float* W2d = (const float*)d_in[15];
    const float* b2d = (const float*)d_in[16];
    const float* a2  = (const float*)d_in[17];
    const float* Wr2 = (const float*)d_in[18];
    const float* br2 = (const float*)d_in[19];

    const int N = in_sizes[0] / 128;
    const int E = in_sizes[1];

    float *FS, *FD, *HA, *HB, *EX, *DEN;
    int* ME;
    cudaGetSymbolAddress((void**)&FS, g_FS);
    cudaGetSymbolAddress((void**)&FD, g_FD);
    cudaGetSymbolAddress((void**)&HA, g_HA);
    cudaGetSymbolAddress((void**)&HB, g_HB);
    cudaGetSymbolAddress((void**)&EX, g_EX);
    cudaGetSymbolAddress((void**)&ME, g_M);
    cudaGetSymbolAddress((void**)&DEN, g_DEN);

    float* out = (float*)d_out;

    const int TB = 256;
    dim3 gemmGrid256(cdiv(N, BM), 256 / BN);
    dim3 gemmGrid192(cdiv(N, BM), 192 / BN);

    // ---------------- Layer 0: x[ N x 128 ] -> HA [ N x 256 ] ----------------
    gemm_bias_kernel<<<gemmGrid256, 256>>>(x, W0s, b0s, FS, N, 128, 256);
    gemm_bias_kernel<<<gemmGrid256, 256>>>(x, W0d, b0d, FD, N, 128, 256);
    init_md_kernel<<<cdiv(N * 4, TB), TB>>>(ME, DEN, N * 4);
    fill_zero_kernel<<<cdiv(N * 64, TB), TB>>>((float4*)HA, N * 64);
    edge_logits_kernel<4, 64><<<cdiv(E * 4, TB), TB>>>(src, dst, FS, FD, a0, EX, ME, E);
    edge_exp_kernel<4><<<cdiv(E * 4, TB), TB>>>(dst, EX, ME, DEN, E);
    edge_scatter_kernel<4, 64><<<cdiv(E * 4, TB), TB>>>(src, dst, FS, EX, DEN, HA, E);
    elu_kernel<<<cdiv(N * 256, TB), TB>>>(HA, N * 256);

    // ---------------- Layer 1: HA [ N x 256 ] -> HB [ N x 256 ] --------------
    gemm_bias_kernel<<<gemmGrid256, 256>>>(HA, W1s, b1s, FS, N, 256, 256);
    gemm_bias_kernel<<<gemmGrid256, 256>>>(HA, W1d, b1d, FD, N, 256, 256);
    init_md_kernel<<<cdiv(N * 4, TB), TB>>>(ME, DEN, N * 4);
    copy_kernel<<<cdiv(N * 64, TB), TB>>>((float4*)HB, (const float4*)HA, N * 64);  // identity residual
    edge_logits_kernel<4, 64><<<cdiv(E * 4, TB), TB>>>(src, dst, FS, FD, a1, EX, ME, E);
    edge_exp_kernel<4><<<cdiv(E * 4, TB), TB>>>(dst, EX, ME, DEN, E);
    edge_scatter_kernel<4, 64><<<cdiv(E * 4, TB), TB>>>(src, dst, FS, EX, DEN, HB, E);
    elu_kernel<<<cdiv(N * 256, TB), TB>>>(HB, N * 256);

    // ---------------- Layer 2: HB [ N x 256 ] -> HA [ N x 192 ] -> out -------
    gemm_bias_kernel<<<gemmGrid192, 256>>>(HB, W2s, b2s, FS, N, 256, 192);
    gemm_bias_kernel<<<gemmGrid192, 256>>>(HB, W2d, b2d, FD, N, 256, 192);
    gemm_bias_kernel<<<gemmGrid192, 256>>>(HB, Wr2, br2, HA, N, 256, 192);  // residual proj -> HA
    init_md_kernel<<<cdiv(N * 6, TB), TB>>>(ME, DEN, N * 6);
    edge_logits_kernel<6, 32><<<cdiv(E * 6, TB), TB>>>(src, dst, FS, FD, a2, EX, ME, E);
    edge_exp_kernel<6><<<cdiv(E * 6, TB), TB>>>(dst, EX, ME, DEN, E);
    edge_scatter_kernel<6, 32><<<cdiv(E * 6, TB), TB>>>(src, dst, FS, EX, DEN, HA, E);
    mean_heads_kernel<<<cdiv(N * 32, TB), TB>>>(HA, out, N * 32);
}

// round 2
// speedup vs baseline: 1.0658x; 1.0658x over previous
#include <cuda_runtime.h>
#include <cuda_bf16.h>
#include <cstdint>

// ---------------------------------------------------------------------------
// GATv2, 3 layers.  N=20000 nodes, E=320000 edges.
// L0: IN=128 -> 4 x 64   (no residual, ELU)
// L1: 256    -> 4 x 64   (identity residual, ELU)
// L2: 256    -> 6 x 32   (linear residual Wr2, no act), mean over heads.
// ---------------------------------------------------------------------------

#define N_MAX   20000
#define E_MAX   320000
#define SLOPE   0.2f

// Scratch (device globals; no allocation allowed)
__device__ __align__(16) float g_FS[N_MAX * 256];
__device__ __align__(16) float g_FD[N_MAX * 256];
__device__ __align__(16) float g_HA[N_MAX * 256];
__device__ __align__(16) float g_HB[N_MAX * 256];
__device__ __align__(16) float g_EX[E_MAX * 6];
__device__ __align__(16) float g_DEN[N_MAX * 6];

static inline int cdiv(int a, int b) { return (a + b - 1) / b; }

// ---------------------------------------------------------------------------
// Multi-output SGEMM: for sel in 0..nOut-1: C[sel] = A @ W[sel] + b[sel]
// A: [Nrows x K] row-major, W: [K x M] row-major.
// 128x64 block tile, BK=16, 256 threads, 8x4 micro-tile, dbl-buffered smem.
// ---------------------------------------------------------------------------
#define BM 128
#define BN 64
#define BK 16
#define BMP (BM + 4)   // padded row for As

struct GemmP {
    const float* W[3];
    const float* b[3];
    float*       C[3];
};

__global__ __launch_bounds__(256) void gemm_multi_kernel(
    const float* __restrict__ A, GemmP P,
    int Nrows, int K, int M, int colBlocksPerOut)
{
    __shared__ float As[2][BK][BMP];
    __shared__ float Bs[2][BK][BN];

    const int tid = threadIdx.x;
    const int sel = blockIdx.y / colBlocksPerOut;
    const int colBase = (blockIdx.y % colBlocksPerOut) * BN;
    const int rowBase = blockIdx.x * BM;

    const float* __restrict__ W    = P.W[sel];
    const float* __restrict__ bias = P.b[sel];
    float*       __restrict__ C    = P.C[sel];

    // A-load mapping: 2 float4 per thread (rows aRow, aRow+64)
    const int aRow = tid / 4;          // 0..63
    const int aK   = (tid % 4) * 4;    // 0,4,8,12
    // B-load mapping: 1 float4 per thread
    const int bRow = tid / 16;         // 0..15
    const int bCol = (tid % 16) * 4;   // 0..60

    // compute mapping: 8 rows x 4 cols per thread
    const int tr = (tid / 16) * 8;     // 0..120
    const int tc = (tid % 16) * 4;     // 0..60

    const int gr0 = rowBase + aRow;
    const int gr1 = rowBase + aRow + 64;

    float acc[8][4] = {};

    float4 pa0, pa1, pb;
    const int steps = K / BK;

    // prefetch step 0
    {
        pa0 = (gr0 < Nrows) ? *reinterpret_cast<const float4*>(&A[(size_t)gr0 * K + aK])
                            : make_float4(0.f, 0.f, 0.f, 0.f);
        pa1 = (gr1 < Nrows) ? *reinterpret_cast<const float4*>(&A[(size_t)gr1 * K + aK])
                            : make_float4(0.f, 0.f, 0.f, 0.f);
        pb  = *reinterpret_cast<const float4*>(&W[(size_t)bRow * M + colBase + bCol]);
        As[0][aK + 0][aRow] = pa0.x;  As[0][aK + 0][aRow + 64] = pa1.x;
        As[0][aK + 1][aRow] = pa0.y;  As[0][aK + 1][aRow + 64] = pa1.y;
        As[0][aK + 2][aRow] = pa0.z;  As[0][aK + 2][aRow + 64] = pa1.z;
        As[0][aK + 3][aRow] = pa0.w;  As[0][aK + 3][aRow + 64] = pa1.w;
        *reinterpret_cast<float4*>(&Bs[0][bRow][bCol]) = pb;
    }
    __syncthreads();

    for (int s = 0; s < steps; s++) {
        const int buf = s & 1;
        // prefetch next tile into registers
        if (s + 1 < steps) {
            const int k0 = (s + 1) * BK;
            pa0 = (gr0 < Nrows) ? *reinterpret_cast<const float4*>(&A[(size_t)gr0 * K + k0 + aK])
                                : make_float4(0.f, 0.f, 0.f, 0.f);
            pa1 = (gr1 < Nrows) ? *reinterpret_cast<const float4*>(&A[(size_t)gr1 * K + k0 + aK])
                                : make_float4(0.f, 0.f, 0.f, 0.f);
            pb  = *reinterpret_cast<const float4*>(&W[(size_t)(k0 + bRow) * M + colBase + bCol]);
        }

        // compute on current buffer
        #pragma unroll
        for (int k = 0; k < BK; k++) {
            float4 a0 = *reinterpret_cast<const float4*>(&As[buf][k][tr]);
            float4 a1 = *reinterpret_cast<const float4*>(&As[buf][k][tr + 4]);
            float4 bv = *reinterpret_cast<const float4*>(&Bs[buf][k][tc]);
            float ar[8] = {a0.x, a0.y, a0.z, a0.w, a1.x, a1.y, a1.z, a1.w};
            float br[4] = {bv.x, bv.y, bv.z, bv.w};
            #pragma unroll
            for (int i = 0; i < 8; i++)
                #pragma unroll
                for (int j = 0; j < 4; j++)
                    acc[i][j] += ar[i] * br[j];
        }

        // store next tile into other buffer
        if (s + 1 < steps) {
            const int nb = buf ^ 1;
            As[nb][aK + 0][aRow] = pa0.x;  As[nb][aK + 0][aRow + 64] = pa1.x;
            As[nb][aK + 1][aRow] = pa0.y;  As[nb][aK + 1][aRow + 64] = pa1.y;
            As[nb][aK + 2][aRow] = pa0.z;  As[nb][aK + 2][aRow + 64] = pa1.z;
            As[nb][aK + 3][aRow] = pa0.w;  As[nb][aK + 3][aRow + 64] = pa1.w;
            *reinterpret_cast<float4*>(&Bs[nb][bRow][bCol]) = pb;
        }
        __syncthreads();
    }

    float4 bv = *reinterpret_cast<const float4*>(&bias[colBase + tc]);
    #pragma unroll
    for (int i = 0; i < 8; i++) {
        int gr = rowBase + tr + i;
        if (gr >= Nrows) continue;
        float4 v;
        v.x = acc[i][0] + bv.x;
        v.y = acc[i][1] + bv.y;
        v.z = acc[i][2] + bv.z;
        v.w = acc[i][3] + bv.w;
        *reinterpret_cast<float4*>(&C[(size_t)gr * M + colBase + tc]) = v;
    }
}

// ---------------------------------------------------------------------------
// Fused edge pass A: logit -> ex = exp(logit) (no max-shift; logits are O(1)),
// store ex, denom += ex.
// ---------------------------------------------------------------------------
template <int H, int D>
__global__ void edge_logits_exp_kernel(
    const int* __restrict__ src, const int* __restrict__ dst,
    const float* __restrict__ FS, const float* __restrict__ FD,
    const float* __restrict__ attn,
    float* __restrict__ ex, float* __restrict__ denom, int E)
{
    int i = blockIdx.x * blockDim.x + threadIdx.x;
    if (i >= E * H) return;
    int e = i / H, h = i % H;
    int s = src[e], d = dst[e];

    const float4* fs = reinterpret_cast<const float4*>(&FS[(size_t)s * (H * D) + h * D]);
    const float4* fd = reinterpret_cast<const float4*>(&FD[(size_t)d * (H * D) + h * D]);
    const float4* at = reinterpret_cast<const float4*>(&attn[h * D]);

    float acc = 0.f;
    #pragma unroll
    for (int q = 0; q < D / 4; q++) {
        float4 a = fs[q], b = fd[q], c = at[q];
        float v;
        v = a.x + b.x; v = (v > 0.f) ? v : SLOPE * v; acc += v * c.x;
        v = a.y + b.y; v = (v > 0.f) ? v : SLOPE * v; acc += v * c.y;
        v = a.z + b.z; v = (v > 0.f) ? v : SLOPE * v; acc += v * c.z;
        v = a.w + b.w; v = (v > 0.f) ? v : SLOPE * v; acc += v * c.w;
    }
    float e_v = __expf(acc);
    ex[i] = e_v;
    atomicAdd(&denom[d * H + h], e_v);
}

// Pass B: out[dst] += feat_src[src] * (ex/denom)  via red.global.add.v4.f32
template <int H, int D>
__global__ void edge_scatter_kernel(
    const int* __restrict__ src, const int* __restrict__ dst,
    const float* __restrict__ FS, const float* __restrict__ ex,
    const float* __restrict__ denom, float* __restrict__ out, int E)
{
    int i = blockIdx.x * blockDim.x + threadIdx.x;
    if (i >= E * H) return;
    int e = i / H, h = i % H;
    int s = src[e], d = dst[e];
    float alpha = ex[i] / denom[d * H + h];

    const float4* fs = reinterpret_cast<const float4*>(&FS[(size_t)s * (H * D) + h * D]);
    float* ob = &out[(size_t)d * (H * D) + h * D];

    #pragma unroll
    for (int q = 0; q < D / 4; q++) {
        float4 a = fs[q];
        asm volatile("red.global.add.v4.f32 [%0], {%1,%2,%3,%4};"
                     :: "l"(ob + q * 4),
                        "f"(a.x * alpha), "f"(a.y * alpha),
                        "f"(a.z * alpha), "f"(a.w * alpha)
                     : "memory");
    }
}

__global__ void elu_kernel(float* __restrict__ p, int n) {
    int i = blockIdx.x * blockDim.x + threadIdx.x;
    if (i >= n) return;
    float v = p[i];
    p[i] = (v > 0.f) ? v : expm1f(v);
}

// mean over H2=6 heads of [N, 6, 32] -> [N, 32]
__global__ void mean_heads_kernel(const float* __restrict__ in, float* __restrict__ out, int n) {
    int i = blockIdx.x * blockDim.x + threadIdx.x;
    if (i >= n) return;
    int node = i / 32, c = i % 32;
    const float* row = &in[(size_t)node * 192 + c];
    float s = 0.f;
    #pragma unroll
    for (int h = 0; h < 6; h++) s += row[h * 32];
    out[i] = s * (1.f / 6.f);
}

// ---------------------------------------------------------------------------
// Host driver
// ---------------------------------------------------------------------------
extern "C" void kernel_launch(void* const* d_in, const int* in_sizes, int n_in,
                              void* d_out, int out_size)
{
    const float* x   = (const float*)d_in[0];
    const int*   src = (const int*)d_in[1];
    const int*   dst = (const int*)d_in[2];
    const float* W0s = (const float*)d_in[3];
    const float* b0s = (const float*)d_in[4];
    const float* W0d = (const float*)d_in[5];
    const float* b0d = (const float*)d_in[6];
    const float* a0  = (const float*)d_in[7];
    const float* W1s = (const float*)d_in[8];
    const float* b1s = (const float*)d_in[9];
    const float* W1d = (const float*)d_in[10];
    const float* b1d = (const float*)d_in[11];
    const float* a1  = (const float*)d_in[12];
    const float* W2s = (const float*)d_in[13];
    const float* b2s = (const float*)d_in[14];
    const float* W2d = (const float*)d_in[15];
    const float* b2d = (const float*)d_in[16];
    const float* a2  = (const float*)d_in[17];
    const float* Wr2 = (const float*)d_in[18];
    const float* br2 = (const float*)d_in[19];

    const int N = in_sizes[0] / 128;
    const int E = in_sizes[1];

    float *FS, *FD, *HA, *HB, *EX, *DEN;
    cudaGetSymbolAddress((void**)&FS, g_FS);
    cudaGetSymbolAddress((void**)&FD, g_FD);
    cudaGetSymbolAddress((void**)&HA, g_HA);
    cudaGetSymbolAddress((void**)&HB, g_HB);
    cudaGetSymbolAddress((void**)&EX, g_EX);
    cudaGetSymbolAddress((void**)&DEN, g_DEN);

    float* out = (float*)d_out;

    const int TB = 256;
    const int rowBlocks = cdiv(N, BM);

    // ---------------- Layer 0: x [N x 128] -> HA [N x 256] ----------------
    {
        GemmP P;
        P.W[0] = W0s; P.b[0] = b0s; P.C[0] = FS;
        P.W[1] = W0d; P.b[1] = b0d; P.C[1] = FD;
        P.W[2] = nullptr; P.b[2] = nullptr; P.C[2] = nullptr;
        dim3 grid(rowBlocks, 2 * (256 / BN));
        gemm_multi_kernel<<<grid, 256>>>(x, P, N, 128, 256, 256 / BN);
    }
    cudaMemsetAsync(DEN, 0, (size_t)N * 4 * sizeof(float), 0);
    cudaMemsetAsync(HA, 0, (size_t)N * 256 * sizeof(float), 0);
    edge_logits_exp_kernel<4, 64><<<cdiv(E * 4, TB), TB>>>(src, dst, FS, FD, a0, EX, DEN, E);
    edge_scatter_kernel<4, 64><<<cdiv(E * 4, TB), TB>>>(src, dst, FS, EX, DEN, HA, E);
    elu_kernel<<<cdiv(N * 256, TB), TB>>>(HA, N * 256);

    // ---------------- Layer 1: HA [N x 256] -> HB [N x 256] ----------------
    {
        GemmP P;
        P.W[0] = W1s; P.b[0] = b1s; P.C[0] = FS;
        P.W[1] = W1d; P.b[1] = b1d; P.C[1] = FD;
        P.W[2] = nullptr; P.b[2] = nullptr; P.C[2] = nullptr;
        dim3 grid(rowBlocks, 2 * (256 / BN));
        gemm_multi_kernel<<<grid, 256>>>(HA, P, N, 256, 256, 256 / BN);
    }
    cudaMemsetAsync(DEN, 0, (size_t)N * 4 * sizeof(float), 0);
    cudaMemcpyAsync(HB, HA, (size_t)N * 256 * sizeof(float), cudaMemcpyDeviceToDevice, 0);
    edge_logits_exp_kernel<4, 64><<<cdiv(E * 4, TB), TB>>>(src, dst, FS, FD, a1, EX, DEN, E);
    edge_scatter_kernel<4, 64><<<cdiv(E * 4, TB), TB>>>(src, dst, FS, EX, DEN, HB, E);
    elu_kernel<<<cdiv(N * 256, TB), TB>>>(HB, N * 256);

    // ---------------- Layer 2: HB [N x 256] -> HA [N x 192] -> out ---------
    {
        GemmP P;
        P.W[0] = W2s; P.b[0] = b2s; P.C[0] = FS;
        P.W[1] = W2d; P.b[1] = b2d; P.C[1] = FD;
        P.W[2] = Wr2; P.b[2] = br2; P.C[2] = HA;   // residual projection
        dim3 grid(rowBlocks, 3 * (192 / BN));
        gemm_multi_kernel<<<grid, 256>>>(HB, P, N, 256, 192, 192 / BN);
    }
    cudaMemsetAsync(DEN, 0, (size_t)N * 6 * sizeof(float), 0);
    edge_logits_exp_kernel<6, 32><<<cdiv(E * 6, TB), TB>>>(src, dst, FS, FD, a2, EX, DEN, E);
    edge_scatter_kernel<6, 32><<<cdiv(E * 6, TB), TB>>>(src, dst, FS, EX, DEN, HA, E);
    mean_heads_kernel<<<cdiv(N * 32, TB), TB>>>(HA, out, N * 32);
}

// round 3
// speedup vs baseline: 2.3367x; 2.1923x over previous
#include <cuda_runtime.h>
#include <cuda_bf16.h>
#include <cstdint>

// ---------------------------------------------------------------------------
// GATv2, 3 layers.  N=20000 nodes, E=320000 edges.
// CSR-by-dst gather formulation: zero feature atomics.
// ---------------------------------------------------------------------------

#define N_MAX   20000
#define E_MAX   320000
#define SLOPE   0.2f

__device__ __align__(16) float g_FS[N_MAX * 256];
__device__ __align__(16) float g_FD[N_MAX * 256];
__device__ __align__(16) float g_HA[N_MAX * 256];
__device__ __align__(16) float g_HB[N_MAX * 256];
__device__ int g_CNT[N_MAX];
__device__ int g_ROWPTR[N_MAX + 1];
__device__ int g_CURS[N_MAX];
__device__ int g_COL[E_MAX];

static inline int cdiv(int a, int b) { return (a + b - 1) / b; }

// ---------------------------------------------------------------------------
// CSR build
// ---------------------------------------------------------------------------
__global__ void hist_kernel(const int* __restrict__ dst, int* __restrict__ cnt, int E) {
    int e = blockIdx.x * blockDim.x + threadIdx.x;
    if (e < E) atomicAdd(&cnt[dst[e]], 1);
}

__global__ __launch_bounds__(1024) void scan_kernel(
    const int* __restrict__ cnt, int* __restrict__ rowptr, int* __restrict__ curs, int n)
{
    __shared__ int part[1024];
    const int t = threadIdx.x;
    const int CH = (n + 1023) / 1024;
    const int base = t * CH;
    int s = 0;
    for (int i = 0; i < CH; i++) {
        int idx = base + i;
        if (idx < n) s += cnt[idx];
    }
    part[t] = s;
    __syncthreads();
    // Hillis-Steele inclusive scan
    for (int off = 1; off < 1024; off <<= 1) {
        int v = (t >= off) ? part[t - off] : 0;
        __syncthreads();
        part[t] += v;
        __syncthreads();
    }
    int run = (t > 0) ? part[t - 1] : 0;   // exclusive prefix for this chunk
    for (int i = 0; i < CH; i++) {
        int idx = base + i;
        if (idx < n) {
            rowptr[idx] = run;
            curs[idx]   = run;
            run += cnt[idx];
        }
    }
    if (t == 1023) rowptr[n] = part[1023];
}

__global__ void fill_kernel(const int* __restrict__ src, const int* __restrict__ dst,
                            int* __restrict__ curs, int* __restrict__ col, int E) {
    int e = blockIdx.x * blockDim.x + threadIdx.x;
    if (e < E) {
        int pos = atomicAdd(&curs[dst[e]], 1);
        col[pos] = src[e];
    }
}

// ---------------------------------------------------------------------------
// Multi-output SGEMM (unchanged from R1): 128x64 tile, 8x4 micro, dbl-buffered
// ---------------------------------------------------------------------------
#define BM 128
#define BN 64
#define BK 16
#define BMP (BM + 4)

struct GemmP {
    const float* W[3];
    const float* b[3];
    float*       C[3];
};

__global__ __launch_bounds__(256) void gemm_multi_kernel(
    const float* __restrict__ A, GemmP P,
    int Nrows, int K, int M, int colBlocksPerOut)
{
    __shared__ float As[2][BK][BMP];
    __shared__ float Bs[2][BK][BN];

    const int tid = threadIdx.x;
    const int sel = blockIdx.y / colBlocksPerOut;
    const int colBase = (blockIdx.y % colBlocksPerOut) * BN;
    const int rowBase = blockIdx.x * BM;

    const float* __restrict__ W    = P.W[sel];
    const float* __restrict__ bias = P.b[sel];
    float*       __restrict__ C    = P.C[sel];

    const int aRow = tid / 4;
    const int aK   = (tid % 4) * 4;
    const int bRow = tid / 16;
    const int bCol = (tid % 16) * 4;
    const int tr = (tid / 16) * 8;
    const int tc = (tid % 16) * 4;

    const int gr0 = rowBase + aRow;
    const int gr1 = rowBase + aRow + 64;

    float acc[8][4] = {};
    float4 pa0, pa1, pb;
    const int steps = K / BK;

    {
        pa0 = (gr0 < Nrows) ? *reinterpret_cast<const float4*>(&A[(size_t)gr0 * K + aK])
                            : make_float4(0.f, 0.f, 0.f, 0.f);
        pa1 = (gr1 < Nrows) ? *reinterpret_cast<const float4*>(&A[(size_t)gr1 * K + aK])
                            : make_float4(0.f, 0.f, 0.f, 0.f);
        pb  = *reinterpret_cast<const float4*>(&W[(size_t)bRow * M + colBase + bCol]);
        As[0][aK + 0][aRow] = pa0.x;  As[0][aK + 0][aRow + 64] = pa1.x;
        As[0][aK + 1][aRow] = pa0.y;  As[0][aK + 1][aRow + 64] = pa1.y;
        As[0][aK + 2][aRow] = pa0.z;  As[0][aK + 2][aRow + 64] = pa1.z;
        As[0][aK + 3][aRow] = pa0.w;  As[0][aK + 3][aRow + 64] = pa1.w;
        *reinterpret_cast<float4*>(&Bs[0][bRow][bCol]) = pb;
    }
    __syncthreads();

    for (int s = 0; s < steps; s++) {
        const int buf = s & 1;
        if (s + 1 < steps) {
            const int k0 = (s + 1) * BK;
            pa0 = (gr0 < Nrows) ? *reinterpret_cast<const float4*>(&A[(size_t)gr0 * K + k0 + aK])
                                : make_float4(0.f, 0.f, 0.f, 0.f);
            pa1 = (gr1 < Nrows) ? *reinterpret_cast<const float4*>(&A[(size_t)gr1 * K + k0 + aK])
                                : make_float4(0.f, 0.f, 0.f, 0.f);
            pb  = *reinterpret_cast<const float4*>(&W[(size_t)(k0 + bRow) * M + colBase + bCol]);
        }

        #pragma unroll
        for (int k = 0; k < BK; k++) {
            float4 a0 = *reinterpret_cast<const float4*>(&As[buf][k][tr]);
            float4 a1 = *reinterpret_cast<const float4*>(&As[buf][k][tr + 4]);
            float4 bv = *reinterpret_cast<const float4*>(&Bs[buf][k][tc]);
            float ar[8] = {a0.x, a0.y, a0.z, a0.w, a1.x, a1.y, a1.z, a1.w};
            float br[4] = {bv.x, bv.y, bv.z, bv.w};
            #pragma unroll
            for (int i = 0; i < 8; i++)
                #pragma unroll
                for (int j = 0; j < 4; j++)
                    acc[i][j] += ar[i] * br[j];
        }

        if (s + 1 < steps) {
            const int nb = buf ^ 1;
            As[nb][aK + 0][aRow] = pa0.x;  As[nb][aK + 0][aRow + 64] = pa1.x;
            As[nb][aK + 1][aRow] = pa0.y;  As[nb][aK + 1][aRow + 64] = pa1.y;
            As[nb][aK + 2][aRow] = pa0.z;  As[nb][aK + 2][aRow + 64] = pa1.z;
            As[nb][aK + 3][aRow] = pa0.w;  As[nb][aK + 3][aRow + 64] = pa1.w;
            *reinterpret_cast<float4*>(&Bs[nb][bRow][bCol]) = pb;
        }
        __syncthreads();
    }

    float4 bv = *reinterpret_cast<const float4*>(&bias[colBase + tc]);
    #pragma unroll
    for (int i = 0; i < 8; i++) {
        int gr = rowBase + tr + i;
        if (gr >= Nrows) continue;
        float4 v;
        v.x = acc[i][0] + bv.x;
        v.y = acc[i][1] + bv.y;
        v.z = acc[i][2] + bv.z;
        v.w = acc[i][3] + bv.w;
        *reinterpret_cast<float4*>(&C[(size_t)gr * M + colBase + tc]) = v;
    }
}

// ---------------------------------------------------------------------------
// Fused per-node aggregation, layers 0/1 (H=4, D=64).
// One block per node, warp w = head w, lane covers dims lane and lane+32.
// RES: 0 = no residual, 1 = identity residual (read from 'resid').
// Epilogue: ELU.
// ---------------------------------------------------------------------------
template <int RES>
__global__ __launch_bounds__(128) void gat_agg_h4d64_kernel(
    const int* __restrict__ rowptr, const int* __restrict__ col,
    const float* __restrict__ FS, const float* __restrict__ FD,
    const float* __restrict__ attn,
    const float* __restrict__ resid, float* __restrict__ out)
{
    const int node = blockIdx.x;
    const int w = threadIdx.x >> 5;       // head 0..3
    const int lane = threadIdx.x & 31;

    const int off = w * 64 + lane;
    const float fd0 = FD[(size_t)node * 256 + off];
    const float fd1 = FD[(size_t)node * 256 + off + 32];
    const float at0 = __ldg(&attn[w * 64 + lane]);
    const float at1 = __ldg(&attn[w * 64 + lane + 32]);

    float s0 = 0.f, s1 = 0.f, den = 0.f;

    const int pEnd = rowptr[node + 1];
    for (int p = rowptr[node]; p < pEnd; p++) {
        const int sn = col[p];
        const float f0 = FS[(size_t)sn * 256 + off];
        const float f1 = FS[(size_t)sn * 256 + off + 32];
        float v0 = f0 + fd0; v0 = (v0 > 0.f) ? v0 : SLOPE * v0;
        float v1 = f1 + fd1; v1 = (v1 > 0.f) ? v1 : SLOPE * v1;
        float t = v0 * at0 + v1 * at1;
        #pragma unroll
        for (int o = 16; o > 0; o >>= 1) t += __shfl_xor_sync(0xffffffffu, t, o);
        const float ex = __expf(t);
        den += ex;
        s0 += f0 * ex;
        s1 += f1 * ex;
    }

    const float inv = (den > 0.f) ? (1.f / den) : 0.f;
    float o0 = s0 * inv;
    float o1 = s1 * inv;
    if (RES) {
        o0 += resid[(size_t)node * 256 + off];
        o1 += resid[(size_t)node * 256 + off + 32];
    }
    o0 = (o0 > 0.f) ? o0 : expm1f(o0);
    o1 = (o1 > 0.f) ? o1 : expm1f(o1);
    out[(size_t)node * 256 + off]      = o0;
    out[(size_t)node * 256 + off + 32] = o1;
}

// ---------------------------------------------------------------------------
// Fused aggregation, layer 2 (H=6, D=32) + linear residual + head mean.
// One block (192 threads = 6 warps) per node; warp w = head.
// ---------------------------------------------------------------------------
__global__ __launch_bounds__(192) void gat_agg_l2_kernel(
    const int* __restrict__ rowptr, const int* __restrict__ col,
    const float* __restrict__ FS, const float* __restrict__ FD,
    const float* __restrict__ attn,
    const float* __restrict__ resid, float* __restrict__ out)
{
    __shared__ float sm[192];
    const int node = blockIdx.x;
    const int w = threadIdx.x / 32;       // head 0..5
    const int lane = threadIdx.x & 31;

    const int off = w * 32 + lane;
    const float fd = FD[(size_t)node * 192 + off];
    const float at = __ldg(&attn[off]);

    float s = 0.f, den = 0.f;

    const int pEnd = rowptr[node + 1];
    for (int p = rowptr[node]; p < pEnd; p++) {
        const int sn = col[p];
        const float f = FS[(size_t)sn * 192 + off];
        float v = f + fd; v = (v > 0.f) ? v : SLOPE * v;
        float t = v * at;
        #pragma unroll
        for (int o = 16; o > 0; o >>= 1) t += __shfl_xor_sync(0xffffffffu, t, o);
        const float ex = __expf(t);
        den += ex;
        s += f * ex;
    }

    const float inv = (den > 0.f) ? (1.f / den) : 0.f;
    sm[off] = s * inv + resid[(size_t)node * 192 + off];
    __syncthreads();

    if (w == 0) {
        float m = 0.f;
        #pragma unroll
        for (int h = 0; h < 6; h++) m += sm[h * 32 + lane];
        out[(size_t)node * 32 + lane] = m * (1.f / 6.f);
    }
}

// ---------------------------------------------------------------------------
// Host driver
// ---------------------------------------------------------------------------
extern "C" void kernel_launch(void* const* d_in, const int* in_sizes, int n_in,
                              void* d_out, int out_size)
{
    const float* x   = (const float*)d_in[0];
    const int*   src = (const int*)d_in[1];
    const int*   dst = (const int*)d_in[2];
    const float* W0s = (const float*)d_in[3];
    const float* b0s = (const float*)d_in[4];
    const float* W0d = (const float*)d_in[5];
    const float* b0d = (const float*)d_in[6];
    const float* a0  = (const float*)d_in[7];
    const float* W1s = (const float*)d_in[8];
    const float* b1s = (const float*)d_in[9];
    const float* W1d = (const float*)d_in[10];
    const float* b1d = (const float*)d_in[11];
    const float* a1  = (const float*)d_in[12];
    const float* W2s = (const float*)d_in[13];
    const float* b2s = (const float*)d_in[14];
    const float* W2d = (const float*)d_in[15];
    const float* b2d = (const float*)d_in[16];
    const float* a2  = (const float*)d_in[17];
    const float* Wr2 = (const float*)d_in[18];
    const float* br2 = (const float*)d_in[19];

    const int N = in_sizes[0] / 128;
    const int E = in_sizes[1];

    float *FS, *FD, *HA, *HB;
    int *CNT, *ROWPTR, *CURS, *COL;
    cudaGetSymbolAddress((void**)&FS, g_FS);
    cudaGetSymbolAddress((void**)&FD, g_FD);
    cudaGetSymbolAddress((void**)&HA, g_HA);
    cudaGetSymbolAddress((void**)&HB, g_HB);
    cudaGetSymbolAddress((void**)&CNT, g_CNT);
    cudaGetSymbolAddress((void**)&ROWPTR, g_ROWPTR);
    cudaGetSymbolAddress((void**)&CURS, g_CURS);
    cudaGetSymbolAddress((void**)&COL, g_COL);

    float* out = (float*)d_out;

    const int TB = 256;
    const int rowBlocks = cdiv(N, BM);

    // ---- CSR build (by dst) ----
    cudaMemsetAsync(CNT, 0, (size_t)N * sizeof(int), 0);
    hist_kernel<<<cdiv(E, TB), TB>>>(dst, CNT, E);
    scan_kernel<<<1, 1024>>>(CNT, ROWPTR, CURS, N);
    fill_kernel<<<cdiv(E, TB), TB>>>(src, dst, CURS, COL, E);

    // ---------------- Layer 0 ----------------
    {
        GemmP P;
        P.W[0] = W0s; P.b[0] = b0s; P.C[0] = FS;
        P.W[1] = W0d; P.b[1] = b0d; P.C[1] = FD;
        P.W[2] = nullptr; P.b[2] = nullptr; P.C[2] = nullptr;
        dim3 grid(rowBlocks, 2 * (256 / BN));
        gemm_multi_kernel<<<grid, 256>>>(x, P, N, 128, 256, 256 / BN);
    }
    gat_agg_h4d64_kernel<0><<<N, 128>>>(ROWPTR, COL, FS, FD, a0, nullptr, HA);

    // ---------------- Layer 1 ----------------
    {
        GemmP P;
        P.W[0] = W1s; P.b[0] = b1s; P.C[0] = FS;
        P.W[1] = W1d; P.b[1] = b1d; P.C[1] = FD;
        P.W[2] = nullptr; P.b[2] = nullptr; P.C[2] = nullptr;
        dim3 grid(rowBlocks, 2 * (256 / BN));
        gemm_multi_kernel<<<grid, 256>>>(HA, P, N, 256, 256, 256 / BN);
    }
    gat_agg_h4d64_kernel<1><<<N, 128>>>(ROWPTR, COL, FS, FD, a1, HA, HB);

    // ---------------- Layer 2 ----------------
    {
        GemmP P;
        P.W[0] = W2s; P.b[0] = b2s; P.C[0] = FS;
        P.W[1] = W2d; P.b[1] = b2d; P.C[1] = FD;
        P.W[2] = Wr2; P.b[2] = br2; P.C[2] = HA;   // residual projection
        dim3 grid(rowBlocks, 3 * (192 / BN));
        gemm_multi_kernel<<<grid, 256>>>(HB, P, N, 256, 192, 192 / BN);
    }
    gat_agg_l2_kernel<<<N, 192>>>(ROWPTR, COL, FS, FD, a2, HA, out);
}

// round 4
// speedup vs baseline: 2.3459x; 1.0040x over previous
#include <cuda_runtime.h>
#include <cuda_bf16.h>
#include <cstdint>

// ---------------------------------------------------------------------------
// GATv2, 3 layers.  N=20000 nodes, E=320000 edges.  CSR gather formulation.
// ---------------------------------------------------------------------------

#define N_MAX   20000
#define E_MAX   320000
#define SLOPE   0.2f

__device__ __align__(16) float g_FS[N_MAX * 256];
__device__ __align__(16) float g_FD[N_MAX * 256];
__device__ __align__(16) float g_HA[N_MAX * 256];
__device__ __align__(16) float g_HB[N_MAX * 256];
__device__ int g_CNT[N_MAX];
__device__ int g_ROWPTR[N_MAX + 1];
__device__ int g_CURS[N_MAX];
__device__ int g_COL[E_MAX];

static inline int cdiv(int a, int b) { return (a + b - 1) / b; }

// ---------------------------------------------------------------------------
// CSR build
// ---------------------------------------------------------------------------
__global__ void hist_kernel(const int* __restrict__ dst, int* __restrict__ cnt, int E) {
    int e = blockIdx.x * blockDim.x + threadIdx.x;
    if (e < E) atomicAdd(&cnt[dst[e]], 1);
}

__global__ __launch_bounds__(1024) void scan_kernel(
    const int* __restrict__ cnt, int* __restrict__ rowptr, int* __restrict__ curs, int n)
{
    __shared__ int part[1024];
    const int t = threadIdx.x;
    const int CH = (n + 1023) / 1024;
    const int base = t * CH;
    int s = 0;
    for (int i = 0; i < CH; i++) {
        int idx = base + i;
        if (idx < n) s += cnt[idx];
    }
    part[t] = s;
    __syncthreads();
    for (int off = 1; off < 1024; off <<= 1) {
        int v = (t >= off) ? part[t - off] : 0;
        __syncthreads();
        part[t] += v;
        __syncthreads();
    }
    int run = (t > 0) ? part[t - 1] : 0;
    for (int i = 0; i < CH; i++) {
        int idx = base + i;
        if (idx < n) {
            rowptr[idx] = run;
            curs[idx]   = run;
            run += cnt[idx];
        }
    }
    if (t == 1023) rowptr[n] = part[1023];
}

__global__ void fill_kernel(const int* __restrict__ src, const int* __restrict__ dst,
                            int* __restrict__ curs, int* __restrict__ col, int E) {
    int e = blockIdx.x * blockDim.x + threadIdx.x;
    if (e < E) {
        int pos = atomicAdd(&curs[dst[e]], 1);
        col[pos] = src[e];
    }
}

// ---------------------------------------------------------------------------
// 128x128 multi-output SGEMM (BK=8, 8x8 micro in split 4+4 layout).
// For L0/L1 (M=256).  256 threads, dbl-buffered smem, register prefetch.
// ---------------------------------------------------------------------------
#define GM 128
#define GN 128
#define GK 8
#define GMP (GM + 4)

struct GemmP {
    const float* W[3];
    const float* b[3];
    float*       C[3];
};

__global__ __launch_bounds__(256) void gemm128_kernel(
    const float* __restrict__ A, GemmP P,
    int Nrows, int K, int M, int colBlocksPerOut)
{
    __shared__ float As[2][GK][GMP];
    __shared__ float Bs[2][GK][GN];

    const int tid = threadIdx.x;
    const int sel = blockIdx.y / colBlocksPerOut;
    const int colBase = (blockIdx.y % colBlocksPerOut) * GN;
    const int rowBase = blockIdx.x * GM;

    const float* __restrict__ W    = P.W[sel];
    const float* __restrict__ bias = P.b[sel];
    float*       __restrict__ C    = P.C[sel];

    // A-load: 1 float4/thread
    const int aRow = tid / 2;          // 0..127
    const int aK   = (tid % 2) * 4;    // 0,4
    // B-load: 1 float4/thread
    const int bRow = tid / 32;         // 0..7
    const int bCol = (tid % 32) * 4;   // 0..124
    // compute: rows {tr..tr+3, tr+64..}, cols {tc..tc+3, tc+64..}
    const int tr = (tid / 16) * 4;     // 0..60
    const int tc = (tid % 16) * 4;     // 0..60

    const int gr = rowBase + aRow;

    float acc[8][8] = {};
    float4 pa, pb;
    const int steps = K / GK;

    {
        pa = (gr < Nrows) ? *reinterpret_cast<const float4*>(&A[(size_t)gr * K + aK])
                          : make_float4(0.f, 0.f, 0.f, 0.f);
        pb = *reinterpret_cast<const float4*>(&W[(size_t)bRow * M + colBase + bCol]);
        As[0][aK + 0][aRow] = pa.x;
        As[0][aK + 1][aRow] = pa.y;
        As[0][aK + 2][aRow] = pa.z;
        As[0][aK + 3][aRow] = pa.w;
        *reinterpret_cast<float4*>(&Bs[0][bRow][bCol]) = pb;
    }
    __syncthreads();

    for (int s = 0; s < steps; s++) {
        const int buf = s & 1;
        if (s + 1 < steps) {
            const int k0 = (s + 1) * GK;
            pa = (gr < Nrows) ? *reinterpret_cast<const float4*>(&A[(size_t)gr * K + k0 + aK])
                              : make_float4(0.f, 0.f, 0.f, 0.f);
            pb = *reinterpret_cast<const float4*>(&W[(size_t)(k0 + bRow) * M + colBase + bCol]);
        }

        #pragma unroll
        for (int k = 0; k < GK; k++) {
            float4 a0 = *reinterpret_cast<const float4*>(&As[buf][k][tr]);
            float4 a1 = *reinterpret_cast<const float4*>(&As[buf][k][tr + 64]);
            float4 b0 = *reinterpret_cast<const float4*>(&Bs[buf][k][tc]);
            float4 b1 = *reinterpret_cast<const float4*>(&Bs[buf][k][tc + 64]);
            float ar[8] = {a0.x, a0.y, a0.z, a0.w, a1.x, a1.y, a1.z, a1.w};
            float br[8] = {b0.x, b0.y, b0.z, b0.w, b1.x, b1.y, b1.z, b1.w};
            #pragma unroll
            for (int i = 0; i < 8; i++)
                #pragma unroll
                for (int j = 0; j < 8; j++)
                    acc[i][j] += ar[i] * br[j];
        }

        if (s + 1 < steps) {
            const int nb = buf ^ 1;
            As[nb][aK + 0][aRow] = pa.x;
            As[nb][aK + 1][aRow] = pa.y;
            As[nb][aK + 2][aRow] = pa.z;
            As[nb][aK + 3][aRow] = pa.w;
            *reinterpret_cast<float4*>(&Bs[nb][bRow][bCol]) = pb;
        }
        __syncthreads();
    }

    float4 bv0 = *reinterpret_cast<const float4*>(&bias[colBase + tc]);
    float4 bv1 = *reinterpret_cast<const float4*>(&bias[colBase + tc + 64]);
    #pragma unroll
    for (int i = 0; i < 8; i++) {
        const int r = tr + ((i < 4) ? i : (60 + i));  // tr+i or tr+64+(i-4)
        const int grow = rowBase + r;
        if (grow >= Nrows) continue;
        float4 v0, v1;
        v0.x = acc[i][0] + bv0.x;  v0.y = acc[i][1] + bv0.y;
        v0.z = acc[i][2] + bv0.z;  v0.w = acc[i][3] + bv0.w;
        v1.x = acc[i][4] + bv1.x;  v1.y = acc[i][5] + bv1.y;
        v1.z = acc[i][6] + bv1.z;  v1.w = acc[i][7] + bv1.w;
        *reinterpret_cast<float4*>(&C[(size_t)grow * M + colBase + tc])      = v0;
        *reinterpret_cast<float4*>(&C[(size_t)grow * M + colBase + tc + 64]) = v1;
    }
}

// ---------------------------------------------------------------------------
// 128x64 multi-output SGEMM (BK=16, 8x4 micro) — used for L2 (M=192).
// ---------------------------------------------------------------------------
#define BM 128
#define BN 64
#define BK 16
#define BMP (BM + 4)

__global__ __launch_bounds__(256) void gemm_multi_kernel(
    const float* __restrict__ A, GemmP P,
    int Nrows, int K, int M, int colBlocksPerOut)
{
    __shared__ float As[2][BK][BMP];
    __shared__ float Bs[2][BK][BN];

    const int tid = threadIdx.x;
    const int sel = blockIdx.y / colBlocksPerOut;
    const int colBase = (blockIdx.y % colBlocksPerOut) * BN;
    const int rowBase = blockIdx.x * BM;

    const float* __restrict__ W    = P.W[sel];
    const float* __restrict__ bias = P.b[sel];
    float*       __restrict__ C    = P.C[sel];

    const int aRow = tid / 4;
    const int aK   = (tid % 4) * 4;
    const int bRow = tid / 16;
    const int bCol = (tid % 16) * 4;
    const int tr = (tid / 16) * 8;
    const int tc = (tid % 16) * 4;

    const int gr0 = rowBase + aRow;
    const int gr1 = rowBase + aRow + 64;

    float acc[8][4] = {};
    float4 pa0, pa1, pb;
    const int steps = K / BK;

    {
        pa0 = (gr0 < Nrows) ? *reinterpret_cast<const float4*>(&A[(size_t)gr0 * K + aK])
                            : make_float4(0.f, 0.f, 0.f, 0.f);
        pa1 = (gr1 < Nrows) ? *reinterpret_cast<const float4*>(&A[(size_t)gr1 * K + aK])
                            : make_float4(0.f, 0.f, 0.f, 0.f);
        pb  = *reinterpret_cast<const float4*>(&W[(size_t)bRow * M + colBase + bCol]);
        As[0][aK + 0][aRow] = pa0.x;  As[0][aK + 0][aRow + 64] = pa1.x;
        As[0][aK + 1][aRow] = pa0.y;  As[0][aK + 1][aRow + 64] = pa1.y;
        As[0][aK + 2][aRow] = pa0.z;  As[0][aK + 2][aRow + 64] = pa1.z;
        As[0][aK + 3][aRow] = pa0.w;  As[0][aK + 3][aRow + 64] = pa1.w;
        *reinterpret_cast<float4*>(&Bs[0][bRow][bCol]) = pb;
    }
    __syncthreads();

    for (int s = 0; s < steps; s++) {
        const int buf = s & 1;
        if (s + 1 < steps) {
            const int k0 = (s + 1) * BK;
            pa0 = (gr0 < Nrows) ? *reinterpret_cast<const float4*>(&A[(size_t)gr0 * K + k0 + aK])
                                : make_float4(0.f, 0.f, 0.f, 0.f);
            pa1 = (gr1 < Nrows) ? *reinterpret_cast<const float4*>(&A[(size_t)gr1 * K + k0 + aK])
                                : make_float4(0.f, 0.f, 0.f, 0.f);
            pb  = *reinterpret_cast<const float4*>(&W[(size_t)(k0 + bRow) * M + colBase + bCol]);
        }

        #pragma unroll
        for (int k = 0; k < BK; k++) {
            float4 a0 = *reinterpret_cast<const float4*>(&As[buf][k][tr]);
            float4 a1 = *reinterpret_cast<const float4*>(&As[buf][k][tr + 4]);
            float4 bv = *reinterpret_cast<const float4*>(&Bs[buf][k][tc]);
            float ar[8] = {a0.x, a0.y, a0.z, a0.w, a1.x, a1.y, a1.z, a1.w};
            float br[4] = {bv.x, bv.y, bv.z, bv.w};
            #pragma unroll
            for (int i = 0; i < 8; i++)
                #pragma unroll
                for (int j = 0; j < 4; j++)
                    acc[i][j] += ar[i] * br[j];
        }

        if (s + 1 < steps) {
            const int nb = buf ^ 1;
            As[nb][aK + 0][aRow] = pa0.x;  As[nb][aK + 0][aRow + 64] = pa1.x;
            As[nb][aK + 1][aRow] = pa0.y;  As[nb][aK + 1][aRow + 64] = pa1.y;
            As[nb][aK + 2][aRow] = pa0.z;  As[nb][aK + 2][aRow + 64] = pa1.z;
            As[nb][aK + 3][aRow] = pa0.w;  As[nb][aK + 3][aRow + 64] = pa1.w;
            *reinterpret_cast<float4*>(&Bs[nb][bRow][bCol]) = pb;
        }
        __syncthreads();
    }

    float4 bv = *reinterpret_cast<const float4*>(&bias[colBase + tc]);
    #pragma unroll
    for (int i = 0; i < 8; i++) {
        int gr = rowBase + tr + i;
        if (gr >= Nrows) continue;
        float4 v;
        v.x = acc[i][0] + bv.x;
        v.y = acc[i][1] + bv.y;
        v.z = acc[i][2] + bv.z;
        v.w = acc[i][3] + bv.w;
        *reinterpret_cast<float4*>(&C[(size_t)gr * M + colBase + tc]) = v;
    }
}

// ---------------------------------------------------------------------------
// Warp butterfly reduce
// ---------------------------------------------------------------------------
__device__ __forceinline__ float warp_sum(float t) {
    #pragma unroll
    for (int o = 16; o > 0; o >>= 1) t += __shfl_xor_sync(0xffffffffu, t, o);
    return t;
}

// ---------------------------------------------------------------------------
// Fused per-node aggregation, layers 0/1 (H=4, D=64), edge loop unrolled x4.
// ---------------------------------------------------------------------------
template <int RES>
__global__ __launch_bounds__(128) void gat_agg_h4d64_kernel(
    const int* __restrict__ rowptr, const int* __restrict__ col,
    const float* __restrict__ FS, const float* __restrict__ FD,
    const float* __restrict__ attn,
    const float* __restrict__ resid, float* __restrict__ out)
{
    const int node = blockIdx.x;
    const int w = threadIdx.x >> 5;
    const int lane = threadIdx.x & 31;

    const int off = w * 64 + lane;
    const float fd0 = FD[(size_t)node * 256 + off];
    const float fd1 = FD[(size_t)node * 256 + off + 32];
    const float at0 = __ldg(&attn[w * 64 + lane]);
    const float at1 = __ldg(&attn[w * 64 + lane + 32]);

    float s0 = 0.f, s1 = 0.f, den = 0.f;

    int p = rowptr[node];
    const int pEnd = rowptr[node + 1];

    for (; p + 4 <= pEnd; p += 4) {
        int sn0 = col[p], sn1 = col[p + 1], sn2 = col[p + 2], sn3 = col[p + 3];
        float f00 = FS[(size_t)sn0 * 256 + off], f01 = FS[(size_t)sn0 * 256 + off + 32];
        float f10 = FS[(size_t)sn1 * 256 + off], f11 = FS[(size_t)sn1 * 256 + off + 32];
        float f20 = FS[(size_t)sn2 * 256 + off], f21 = FS[(size_t)sn2 * 256 + off + 32];
        float f30 = FS[(size_t)sn3 * 256 + off], f31 = FS[(size_t)sn3 * 256 + off + 32];

        float v, t0, t1, t2, t3;
        v = f00 + fd0; v = (v > 0.f) ? v : SLOPE * v; t0  = v * at0;
        v = f01 + fd1; v = (v > 0.f) ? v : SLOPE * v; t0 += v * at1;
        v = f10 + fd0; v = (v > 0.f) ? v : SLOPE * v; t1  = v * at0;
        v = f11 + fd1; v = (v > 0.f) ? v : SLOPE * v; t1 += v * at1;
        v = f20 + fd0; v = (v > 0.f) ? v : SLOPE * v; t2  = v * at0;
        v = f21 + fd1; v = (v > 0.f) ? v : SLOPE * v; t2 += v * at1;
        v = f30 + fd0; v = (v > 0.f) ? v : SLOPE * v; t3  = v * at0;
        v = f31 + fd1; v = (v > 0.f) ? v : SLOPE * v; t3 += v * at1;

        #pragma unroll
        for (int o = 16; o > 0; o >>= 1) {
            t0 += __shfl_xor_sync(0xffffffffu, t0, o);
            t1 += __shfl_xor_sync(0xffffffffu, t1, o);
            t2 += __shfl_xor_sync(0xffffffffu, t2, o);
            t3 += __shfl_xor_sync(0xffffffffu, t3, o);
        }
        float e0 = __expf(t0), e1 = __expf(t1), e2 = __expf(t2), e3 = __expf(t3);
        den += (e0 + e1) + (e2 + e3);
        s0 += f00 * e0 + f10 * e1 + f20 * e2 + f30 * e3;
        s1 += f01 * e0 + f11 * e1 + f21 * e2 + f31 * e3;
    }
    for (; p < pEnd; p++) {
        int sn = col[p];
        float f0 = FS[(size_t)sn * 256 + off];
        float f1 = FS[(size_t)sn * 256 + off + 32];
        float v0 = f0 + fd0; v0 = (v0 > 0.f) ? v0 : SLOPE * v0;
        float v1 = f1 + fd1; v1 = (v1 > 0.f) ? v1 : SLOPE * v1;
        float t = warp_sum(v0 * at0 + v1 * at1);
        float ex = __expf(t);
        den += ex; s0 += f0 * ex; s1 += f1 * ex;
    }

    const float inv = (den > 0.f) ? (1.f / den) : 0.f;
    float o0 = s0 * inv;
    float o1 = s1 * inv;
    if (RES) {
        o0 += resid[(size_t)node * 256 + off];
        o1 += resid[(size_t)node * 256 + off + 32];
    }
    o0 = (o0 > 0.f) ? o0 : expm1f(o0);
    o1 = (o1 > 0.f) ? o1 : expm1f(o1);
    out[(size_t)node * 256 + off]      = o0;
    out[(size_t)node * 256 + off + 32] = o1;
}

// ---------------------------------------------------------------------------
// Fused aggregation, layer 2 (H=6, D=32) + linear residual + head mean.
// ---------------------------------------------------------------------------
__global__ __launch_bounds__(192) void gat_agg_l2_kernel(
    const int* __restrict__ rowptr, const int* __restrict__ col,
    const float* __restrict__ FS, const float* __restrict__ FD,
    const float* __restrict__ attn,
    const float* __restrict__ resid, float* __restrict__ out)
{
    __shared__ float sm[192];
    const int node = blockIdx.x;
    const int w = threadIdx.x / 32;
    const int lane = threadIdx.x & 31;

    const int off = w * 32 + lane;
    const float fd = FD[(size_t)node * 192 + off];
    const float at = __ldg(&attn[off]);

    float s = 0.f, den = 0.f;

    int p = rowptr[node];
    const int pEnd = rowptr[node + 1];

    for (; p + 4 <= pEnd; p += 4) {
        int sn0 = col[p], sn1 = col[p + 1], sn2 = col[p + 2], sn3 = col[p + 3];
        float f0 = FS[(size_t)sn0 * 192 + off];
        float f1 = FS[(size_t)sn1 * 192 + off];
        float f2 = FS[(size_t)sn2 * 192 + off];
        float f3 = FS[(size_t)sn3 * 192 + off];
        float v, t0, t1, t2, t3;
        v = f0 + fd; v = (v > 0.f) ? v : SLOPE * v; t0 = v * at;
        v = f1 + fd; v = (v > 0.f) ? v : SLOPE * v; t1 = v * at;
        v = f2 + fd; v = (v > 0.f) ? v : SLOPE * v; t2 = v * at;
        v = f3 + fd; v = (v > 0.f) ? v : SLOPE * v; t3 = v * at;
        #pragma unroll
        for (int o = 16; o > 0; o >>= 1) {
            t0 += __shfl_xor_sync(0xffffffffu, t0, o);
            t1 += __shfl_xor_sync(0xffffffffu, t1, o);
            t2 += __shfl_xor_sync(0xffffffffu, t2, o);
            t3 += __shfl_xor_sync(0xffffffffu, t3, o);
        }
        float e0 = __expf(t0), e1 = __expf(t1), e2 = __expf(t2), e3 = __expf(t3);
        den += (e0 + e1) + (e2 + e3);
        s += f0 * e0 + f1 * e1 + f2 * e2 + f3 * e3;
    }
    for (; p < pEnd; p++) {
        int sn = col[p];
        float f = FS[(size_t)sn * 192 + off];
        float v = f + fd; v = (v > 0.f) ? v : SLOPE * v;
        float t = warp_sum(v * at);
        float ex = __expf(t);
        den += ex; s += f * ex;
    }

    const float inv = (den > 0.f) ? (1.f / den) : 0.f;
    sm[off] = s * inv + resid[(size_t)node * 192 + off];
    __syncthreads();

    if (w == 0) {
        float m = 0.f;
        #pragma unroll
        for (int h = 0; h < 6; h++) m += sm[h * 32 + lane];
        out[(size_t)node * 32 + lane] = m * (1.f / 6.f);
    }
}

// ---------------------------------------------------------------------------
// Host driver
// ---------------------------------------------------------------------------
extern "C" void kernel_launch(void* const* d_in, const int* in_sizes, int n_in,
                              void* d_out, int out_size)
{
    const float* x   = (const float*)d_in[0];
    const int*   src = (const int*)d_in[1];
    const int*   dst = (const int*)d_in[2];
    const float* W0s = (const float*)d_in[3];
    const float* b0s = (const float*)d_in[4];
    const float* W0d = (const float*)d_in[5];
    const float* b0d = (const float*)d_in[6];
    const float* a0  = (const float*)d_in[7];
    const float* W1s = (const float*)d_in[8];
    const float* b1s = (const float*)d_in[9];
    const float* W1d = (const float*)d_in[10];
    const float* b1d = (const float*)d_in[11];
    const float* a1  = (const float*)d_in[12];
    const float* W2s = (const float*)d_in[13];
    const float* b2s = (const float*)d_in[14];
    const float* W2d = (const float*)d_in[15];
    const float* b2d = (const float*)d_in[16];
    const float* a2  = (const float*)d_in[17];
    const float* Wr2 = (const float*)d_in[18];
    const float* br2 = (const float*)d_in[19];

    const int N = in_sizes[0] / 128;
    const int E = in_sizes[1];

    float *FS, *FD, *HA, *HB;
    int *CNT, *ROWPTR, *CURS, *COL;
    cudaGetSymbolAddress((void**)&FS, g_FS);
    cudaGetSymbolAddress((void**)&FD, g_FD);
    cudaGetSymbolAddress((void**)&HA, g_HA);
    cudaGetSymbolAddress((void**)&HB, g_HB);
    cudaGetSymbolAddress((void**)&CNT, g_CNT);
    cudaGetSymbolAddress((void**)&ROWPTR, g_ROWPTR);
    cudaGetSymbolAddress((void**)&CURS, g_CURS);
    cudaGetSymbolAddress((void**)&COL, g_COL);

    float* out = (float*)d_out;

    const int TB = 256;

    // ---- CSR build (by dst) ----
    cudaMemsetAsync(CNT, 0, (size_t)N * sizeof(int), 0);
    hist_kernel<<<cdiv(E, TB), TB>>>(dst, CNT, E);
    scan_kernel<<<1, 1024>>>(CNT, ROWPTR, CURS, N);
    fill_kernel<<<cdiv(E, TB), TB>>>(src, dst, CURS, COL, E);

    // ---------------- Layer 0 ----------------
    {
        GemmP P;
        P.W[0] = W0s; P.b[0] = b0s; P.C[0] = FS;
        P.W[1] = W0d; P.b[1] = b0d; P.C[1] = FD;
        P.W[2] = nullptr; P.b[2] = nullptr; P.C[2] = nullptr;
        dim3 grid(cdiv(N, GM), 2 * (256 / GN));
        gemm128_kernel<<<grid, 256>>>(x, P, N, 128, 256, 256 / GN);
    }
    gat_agg_h4d64_kernel<0><<<N, 128>>>(ROWPTR, COL, FS, FD, a0, nullptr, HA);

    // ---------------- Layer 1 ----------------
    {
        GemmP P;
        P.W[0] = W1s; P.b[0] = b1s; P.C[0] = FS;
        P.W[1] = W1d; P.b[1] = b1d; P.C[1] = FD;
        P.W[2] = nullptr; P.b[2] = nullptr; P.C[2] = nullptr;
        dim3 grid(cdiv(N, GM), 2 * (256 / GN));
        gemm128_kernel<<<grid, 256>>>(HA, P, N, 256, 256, 256 / GN);
    }
    gat_agg_h4d64_kernel<1><<<N, 128>>>(ROWPTR, COL, FS, FD, a1, HA, HB);

    // ---------------- Layer 2 ----------------
    {
        GemmP P;
        P.W[0] = W2s; P.b[0] = b2s; P.C[0] = FS;
        P.W[1] = W2d; P.b[1] = b2d; P.C[1] = FD;
        P.W[2] = Wr2; P.b[2] = br2; P.C[2] = HA;
        dim3 grid(cdiv(N, BM), 3 * (192 / BN));
        gemm_multi_kernel<<<grid, 256>>>(HB, P, N, 256, 192, 192 / BN);
    }
    gat_agg_l2_kernel<<<N, 192>>>(ROWPTR, COL, FS, FD, a2, HA, out);
}